// round 13
// baseline (speedup 1.0000x reference)
#include <cuda_runtime.h>
#include <math.h>
#include <stdint.h>

#define BB 64
#define SS 1024
#define PP 32
#define EE 128
#define HH 256
#define G4 1024
#define NJB 64
#define NBLK 128
#define SWS2 776

#define SM_ACT 0
#define SM_W   24576
#define SM_Z   (SM_W + 16*SWS2)
#define SM_R   (SM_Z + 8192)
#define SM_M   (SM_R + 8192)
#define SMEM_FLOATS (SM_M + 128)
#define SMEM_BYTES (SMEM_FLOATS * 4)

__device__ float    g_xT[SS * EE * BB];
__device__ float    g_h[2 * 2 * HH * BB];
__device__ float    g_bias[2 * G4];
__device__ float    g_Wt[2 * NJB * 16 * 384 * 2];
__device__ unsigned g_spanmaskT[SS * BB];
__device__ int      g_cnt[BB * PP];
__device__ float    g_reps[BB * PP * 2 * HH];
__device__ unsigned g_arrive[2 * NJB];

__global__ void k_prep(const float* bih_f, const float* bhh_f,
                       const float* bih_b, const float* bhh_b,
                       const float* Wih_f, const float* Whh_f,
                       const float* Wih_b, const float* Whh_b) {
    int i0 = blockIdx.x * blockDim.x + threadIdx.x;
    int stride = gridDim.x * blockDim.x;
    if (i0 < 2 * NJB) g_arrive[i0] = 0;
    for (int i = i0; i < 2 * 2 * HH * BB; i += stride) g_h[i] = 0.f;
    for (int i = i0; i < BB * PP;         i += stride) g_cnt[i] = 0;
    for (int i = i0; i < 2 * G4;          i += stride)
        g_bias[i] = (i < G4) ? (bih_f[i] + bhh_f[i]) : (bih_b[i - G4] + bhh_b[i - G4]);
    for (int idx = i0; idx < 2 * NJB * 16 * 384; idx += stride) {
        int k   = idx % 384;
        int r   = idx / 384;
        int c   = r % 16;
        int jb  = (r / 16) % NJB;
        int dir = r / (16 * NJB);
        int zcol = (c >> 2) * HH + jb * 4 + (c & 3);
        const float* Wih = dir ? Wih_b : Wih_f;
        const float* Whh = dir ? Whh_b : Whh_f;
        float v = (k < EE) ? Wih[zcol * EE + k] : Whh[zcol * HH + (k - EE)];
        g_Wt[idx * 2 + 0] = v;
        g_Wt[idx * 2 + 1] = v;
    }
}

__global__ void k_embed(const float* emb, const int* ids) {
    __shared__ float tile[128 * 65];
    __shared__ int sid[64];
    int s = blockIdx.x, t = threadIdx.x;
    if (t < 64) sid[t] = ids[t * SS + s];
    __syncthreads();
    for (int i = t; i < 8192; i += 256) {
        int b = i >> 7, e = i & 127;
        tile[e * 65 + b] = emb[sid[b] * EE + e];
    }
    __syncthreads();
    float* dst = g_xT + s * (EE * BB);
    for (int i = t; i < 8192; i += 256)
        dst[i] = tile[(i >> 6) * 65 + (i & 63)];
}

__global__ void k_span(const int* offmap, const int* positions) {
    int idx = blockIdx.x * blockDim.x + threadIdx.x;
    if (idx >= BB * SS) return;
    int b = idx / SS;
    int s = idx % SS;
    int os = offmap[idx * 2], oe = offmap[idx * 2 + 1];
    unsigned m = 0;
    for (int p = 0; p < PP; p++) {
        int ps = positions[(b * PP + p) * 2];
        int pe = positions[(b * PP + p) * 2 + 1];
        if (os >= ps && oe <= pe) {
            m |= (1u << p);
            atomicAdd(&g_cnt[b * PP + p], 1);
        }
    }
    g_spanmaskT[s * BB + b] = m;
}

__device__ __forceinline__ void ffma2(unsigned long long& d,
                                      unsigned long long a,
                                      unsigned long long b) {
    asm("fma.rn.f32x2 %0, %1, %2, %0;" : "+l"(d) : "l"(a), "l"(b));
}
__device__ __forceinline__ void cpasync16(uint32_t saddr, const void* gaddr) {
    asm volatile("cp.async.cg.shared.global [%0], [%1], 16;" :: "r"(saddr), "l"(gaddr));
}
__device__ __forceinline__ void cpasync_commit() { asm volatile("cp.async.commit_group;"); }
__device__ __forceinline__ void cpasync_wait2()  { asm volatile("cp.async.wait_group 2;"); }
__device__ __forceinline__ void cpasync_wait1()  { asm volatile("cp.async.wait_group 1;"); }
__device__ __forceinline__ void cpasync_wait0()  { asm volatile("cp.async.wait_group 0;"); }
__device__ __forceinline__ void st_release_gpu(unsigned* p, unsigned v) {
    asm volatile("st.release.gpu.global.u32 [%0], %1;" :: "l"(p), "r"(v) : "memory");
}
__device__ __forceinline__ unsigned ld_acquire_gpu(const unsigned* p) {
    unsigned v;
    asm volatile("ld.acquire.gpu.global.u32 %0, [%1];" : "=r"(v) : "l"(p) : "memory");
    return v;
}
__device__ __forceinline__ void barx(int id, int cnt) {
    asm volatile("bar.sync %0, %1;" :: "r"(id), "r"(cnt) : "memory");
}
__device__ __forceinline__ float sigmoidf_(float x) { return 1.f / (1.f + __expf(-x)); }
__device__ __forceinline__ float tanhf_(float x) {
    float xc = fminf(fmaxf(x, -15.f), 15.f);
    float e = __expf(2.f * xc);
    return (e - 1.f) / (e + 1.f);
}

__device__ __forceinline__ void gemm_range(const float* __restrict__ sAct,
                                           const float* __restrict__ sW2,
                                           int ct, int b0, int kbeg, int kend,
                                           unsigned long long acc[4][2]) {
    const float* abase = sAct + b0;
    #pragma unroll 2
    for (int k = kbeg; k < kend; k += 4) {
        ulonglong2 a0 = *(const ulonglong2*)(abase + (k + 0) * BB);
        ulonglong2 a1 = *(const ulonglong2*)(abase + (k + 1) * BB);
        ulonglong2 a2 = *(const ulonglong2*)(abase + (k + 2) * BB);
        ulonglong2 a3 = *(const ulonglong2*)(abase + (k + 3) * BB);
        #pragma unroll
        for (int r = 0; r < 4; r++) {
            const float* wb = sW2 + (ct * 4 + r) * SWS2 + k * 2;
            ulonglong2 w01 = *(const ulonglong2*)(wb);
            ulonglong2 w23 = *(const ulonglong2*)(wb + 4);
            ffma2(acc[r][0], w01.x, a0.x); ffma2(acc[r][1], w01.x, a0.y);
            ffma2(acc[r][0], w01.y, a1.x); ffma2(acc[r][1], w01.y, a1.y);
            ffma2(acc[r][0], w23.x, a2.x); ffma2(acc[r][1], w23.x, a2.y);
            ffma2(acc[r][0], w23.y, a3.x); ffma2(acc[r][1], w23.y, a3.y);
        }
    }
}

extern __shared__ float smem[];

__global__ void __launch_bounds__(512, 1) k_lstm(int nsteps) {
    float*    sAct = smem + SM_ACT;              // [384][64]
    float*    sW2  = smem + SM_W;                // [16][SWS2]
    float*    sZP  = smem + SM_Z;                // [8 kq][16][64]
    float*    sR   = smem + SM_R;                // [32 p][4 u][64 b]
    unsigned* sM   = (unsigned*)(smem + SM_M);   // [2][64]

    const int t   = threadIdx.x;
    const int jb  = blockIdx.x & (NJB - 1);
    const int dir = blockIdx.x >> 6;
    unsigned* slots = g_arrive + dir * NJB;

    {   // weights resident in smem for the whole run
        const float4* wsrc = (const float4*)(g_Wt + (size_t)(dir * NJB + jb) * 16 * 384 * 2);
        float4* wdst = (float4*)sW2;
        for (int i = t; i < 3072; i += 512) {
            int c = i / 192, j = i % 192;
            wdst[c * (SWS2 / 4) + j] = wsrc[i];
        }
    }
    for (int i = t; i < 8192; i += 512) sR[i] = 0.f;

    // roles
    const int kq    = t >> 6;          // warp-pair id 0..7
    const int tp    = t & 63;
    const int ct    = tp >> 4;         // gate 0..3
    const int b0    = (tp & 15) * 4;
    const int hb    = 128 + kq * 32;   // h K-range (32 rows per pair)
    const int xb    = kq * 16;         // x K-range (16 rows per pair)
    const int pbar  = 8 + kq;          // named barrier per pair

    // gates roles (t<256): 1 cell per thread
    const int u  = (t >> 6) & 3;
    const int gb = t & 63;
    float bvg[4];
    if (t < 256) {
        #pragma unroll
        for (int g = 0; g < 4; g++)
            bvg[g] = g_bias[dir * G4 + g * HH + jb * 4 + u];
    }
    float creg = 0.f;

    const uint32_t sact_b = (uint32_t)__cvta_generic_to_shared(sAct);
    const uint32_t sm_b   = (uint32_t)__cvta_generic_to_shared(sM);

    unsigned long long accC[4][2];   // x(s) + h(s) contributions -> partials
    unsigned long long accX[4][2];   // x(s+1) contribution (pipelined)

    // prologue: x(0) + mask(0) [group G0]; x-GEMM(0) -> accC; then prefetch x(1) [X]
    {
        int s0 = dir ? (SS - 1) : 0;
        const float* xsrc = g_xT + (size_t)s0 * (EE * BB);
        #pragma unroll
        for (int i = 0; i < 4; i++) {
            int fi = kq * 1024 + (i * 64 + tp) * 4;
            cpasync16(sact_b + (uint32_t)fi * 4, xsrc + fi);
        }
        if (t < 16)
            cpasync16(sm_b + (uint32_t)t * 16, g_spanmaskT + s0 * BB + t * 4);
        cpasync_commit();
    }
    cpasync_wait0();
    __syncthreads();
    #pragma unroll
    for (int r = 0; r < 4; r++) { accC[r][0] = 0ull; accC[r][1] = 0ull; }
    gemm_range(sAct, sW2, ct, b0, xb, xb + 16, accC);
    barx(pbar, 64);                    // pair done reading x(0) slice
    if (nsteps > 1) {                  // prefetch x(1) [group X]
        int s1 = dir ? (SS - 2) : 1;
        const float* xsrc = g_xT + (size_t)s1 * (EE * BB);
        #pragma unroll
        for (int i = 0; i < 4; i++) {
            int fi = kq * 1024 + (i * 64 + tp) * 4;
            cpasync16(sact_b + (uint32_t)fi * 4, xsrc + fi);
        }
    }
    cpasync_commit();

    for (int step = 0; step < nsteps; step++) {
        const int par = step & 1;

        // 1. slot barrier (only 64 threads poll)
        if (t < NJB) {
            while ((int)ld_acquire_gpu(slots + t) < step) { }
        }
        __syncthreads();

        // 2. issue h staging waves A and B
        {
            const float* hsrc = g_h + (dir * 2 + par) * (HH * BB);
            #pragma unroll
            for (int i = 0; i < 4; i++) {                 // wave A
                int fi = kq * 2048 + (i * 64 + tp) * 4;
                cpasync16(sact_b + (uint32_t)(8192 + fi) * 4, hsrc + fi);
            }
            cpasync_commit();
            #pragma unroll
            for (int i = 4; i < 8; i++) {                 // wave B
                int fi = kq * 2048 + (i * 64 + tp) * 4;
                cpasync16(sact_b + (uint32_t)(8192 + fi) * 4, hsrc + fi);
            }
            cpasync_commit();
        }

        // 3. x-GEMM for step+1 in the h-latency shadow
        //    pending groups here: [X(step+1), A, B] -> wait2 retires X
        cpasync_wait2();
        barx(pbar, 64);
        #pragma unroll
        for (int r = 0; r < 4; r++) { accX[r][0] = 0ull; accX[r][1] = 0ull; }
        if (step + 1 < nsteps)
            gemm_range(sAct, sW2, ct, b0, xb, xb + 16, accX);
        barx(pbar, 64);    // pair done reading x(step+1) slice before overwrite

        // 4. issue X' group: x(step+2) + mask(step+1)
        if (step + 2 < nsteps) {
            int s_nn = dir ? (SS - 3 - step) : (step + 2);
            const float* xsrc = g_xT + (size_t)s_nn * (EE * BB);
            #pragma unroll
            for (int i = 0; i < 4; i++) {
                int fi = kq * 1024 + (i * 64 + tp) * 4;
                cpasync16(sact_b + (uint32_t)fi * 4, xsrc + fi);
            }
        }
        if (t < 16 && step + 1 < nsteps) {
            int s_next = dir ? (SS - 2 - step) : (step + 1);
            cpasync16(sm_b + (uint32_t)((par ^ 1) * 64 + t * 4) * 4,
                      g_spanmaskT + s_next * BB + t * 4);
        }
        cpasync_commit();

        // 5. h-GEMM: wave A (pending [A,B,X'] -> wait2 retires A), then wave B
        cpasync_wait2();
        barx(pbar, 64);
        gemm_range(sAct, sW2, ct, b0, hb, hb + 16, accC);
        cpasync_wait1();
        barx(pbar, 64);
        gemm_range(sAct, sW2, ct, b0, hb + 16, hb + 32, accC);

        // 6. partials -> sZP; rotate accX -> accC; block-wide join
        #pragma unroll
        for (int r = 0; r < 4; r++) {
            float2 lo = *(float2*)&accC[r][0];
            float2 hi = *(float2*)&accC[r][1];
            *(float4*)&sZP[kq * 1024 + (ct * 4 + r) * 64 + b0] =
                make_float4(lo.x, lo.y, hi.x, hi.y);
        }
        #pragma unroll
        for (int r = 0; r < 4; r++) { accC[r][0] = accX[r][0]; accC[r][1] = accX[r][1]; }
        __syncthreads();

        // 7. gates (warps 0-7) -> h publish -> release
        if (t < 256) {
            float z[4];
            #pragma unroll
            for (int g = 0; g < 4; g++) {
                float s = bvg[g];
                #pragma unroll
                for (int q = 0; q < 8; q++)
                    s += sZP[q * 1024 + (g * 4 + u) * 64 + gb];
                z[g] = s;
            }
            float ii = sigmoidf_(z[0]);
            float ff = sigmoidf_(z[1]);
            float gg = tanhf_(z[2]);
            float oo = sigmoidf_(z[3]);
            float cn = ff * creg + ii * gg;
            creg = cn;
            float hn = oo * tanhf_(cn);
            int j = jb * 4 + u;
            __stcg(&g_h[((dir * 2 + (par ^ 1)) * HH + j) * BB + gb], hn);
            barx(1, 256);
            if (t == 0) {
                asm volatile("membar.gl;" ::: "memory");
                st_release_gpu(slots + jb, (unsigned)(step + 1));
            }
            // off-critical-path span accumulation
            unsigned m = sM[par * 64 + gb];
            while (m) {
                int p = __ffs(m) - 1;
                m &= m - 1;
                sR[p * 256 + u * 64 + gb] += hn;
            }
        }
    }

    __syncthreads();
    for (int i = t; i < 8192; i += 512) {
        int p = i >> 8, uu = (i >> 6) & 3, b = i & 63;
        g_reps[(b * PP + p) * (2 * HH) + dir * HH + jb * 4 + uu] = sR[i];
    }
}

__global__ void k_final(const float* fc_w, const float* fc_b,
                        const int* positions, float* out) {
    int bp = blockIdx.x;
    int t = threadIdx.x;
    __shared__ float red[128];
    float s = 0.f;
    for (int d = t; d < 2 * HH; d += 128)
        s += g_reps[bp * (2 * HH) + d] * fc_w[d];
    red[t] = s;
    __syncthreads();
    for (int o = 64; o > 0; o >>= 1) {
        if (t < o) red[t] += red[t + o];
        __syncthreads();
    }
    if (t == 0) {
        int cnt = g_cnt[bp];
        int ps = positions[bp * 2], pe = positions[bp * 2 + 1];
        bool valid = (cnt > 0) && !(ps == 0 && pe == 0);
        float v = valid ? red[0] / fmaxf((float)cnt, 1.f) : 0.f;
        out[bp] = v + fc_b[0];
    }
}

extern "C" void kernel_launch(void* const* d_in, const int* in_sizes, int n_in,
                              void* d_out, int out_size) {
    const float* emb    = (const float*)d_in[0];
    const float* Wih_f  = (const float*)d_in[1];
    const float* Whh_f  = (const float*)d_in[2];
    const float* bih_f  = (const float*)d_in[3];
    const float* bhh_f  = (const float*)d_in[4];
    const float* Wih_b  = (const float*)d_in[5];
    const float* Whh_b  = (const float*)d_in[6];
    const float* bih_b  = (const float*)d_in[7];
    const float* bhh_b  = (const float*)d_in[8];
    const float* fc_w   = (const float*)d_in[9];
    const float* fc_b   = (const float*)d_in[10];
    const int* input_ids = (const int*)d_in[11];
    const int* offmap    = (const int*)d_in[13];
    const int* positions = (const int*)d_in[14];
    float* out = (float*)d_out;

    cudaFuncSetAttribute(k_lstm, cudaFuncAttributeMaxDynamicSharedMemorySize, SMEM_BYTES);

    k_prep<<<1024, 256>>>(bih_f, bhh_f, bih_b, bhh_b, Wih_f, Whh_f, Wih_b, Whh_b);
    k_embed<<<SS, 256>>>(emb, input_ids);
    k_span<<<(BB * SS) / 256, 256>>>(offmap, positions);
    k_lstm<<<NBLK, 512, SMEM_BYTES>>>(SS);
    k_final<<<BB * PP, 128>>>(fc_w, fc_b, positions, out);
}

// round 14
// speedup vs baseline: 1.3291x; 1.3291x over previous
#include <cuda_runtime.h>
#include <math.h>
#include <stdint.h>

#define BB 64
#define SS 1024
#define PP 32
#define EE 128
#define HH 256
#define G4 1024
#define NJB 64
#define NBLK 128
#define SWS2 776

#define SM_ACT 0
#define SM_W   24576
#define SM_Z   (SM_W + 16*SWS2)
#define SM_R   (SM_Z + 8192)
#define SM_M   (SM_R + 8192)
#define SM_MB  (SM_M + 128)
#define SMEM_FLOATS (SM_MB + 8)
#define SMEM_BYTES (SMEM_FLOATS * 4)

__device__ __align__(128) float g_xT[SS * EE * BB];
__device__ __align__(128) float g_h[2 * 2 * HH * BB];
__device__ float    g_bias[2 * G4];
__device__ float    g_Wt[2 * NJB * 16 * 384 * 2];
__device__ unsigned g_spanmaskT[SS * BB];
__device__ int      g_cnt[BB * PP];
__device__ float    g_reps[BB * PP * 2 * HH];
__device__ unsigned g_arrive[2 * NJB];

__global__ void k_prep(const float* bih_f, const float* bhh_f,
                       const float* bih_b, const float* bhh_b,
                       const float* Wih_f, const float* Whh_f,
                       const float* Wih_b, const float* Whh_b) {
    int i0 = blockIdx.x * blockDim.x + threadIdx.x;
    int stride = gridDim.x * blockDim.x;
    if (i0 < 2 * NJB) g_arrive[i0] = 0;
    for (int i = i0; i < 2 * 2 * HH * BB; i += stride) g_h[i] = 0.f;
    for (int i = i0; i < BB * PP;         i += stride) g_cnt[i] = 0;
    for (int i = i0; i < 2 * G4;          i += stride)
        g_bias[i] = (i < G4) ? (bih_f[i] + bhh_f[i]) : (bih_b[i - G4] + bhh_b[i - G4]);
    for (int idx = i0; idx < 2 * NJB * 16 * 384; idx += stride) {
        int k   = idx % 384;
        int r   = idx / 384;
        int c   = r % 16;
        int jb  = (r / 16) % NJB;
        int dir = r / (16 * NJB);
        int zcol = (c >> 2) * HH + jb * 4 + (c & 3);
        const float* Wih = dir ? Wih_b : Wih_f;
        const float* Whh = dir ? Whh_b : Whh_f;
        float v = (k < EE) ? Wih[zcol * EE + k] : Whh[zcol * HH + (k - EE)];
        g_Wt[idx * 2 + 0] = v;
        g_Wt[idx * 2 + 1] = v;
    }
}

__global__ void k_embed(const float* emb, const int* ids) {
    __shared__ float tile[128 * 65];
    __shared__ int sid[64];
    int s = blockIdx.x, t = threadIdx.x;
    if (t < 64) sid[t] = ids[t * SS + s];
    __syncthreads();
    for (int i = t; i < 8192; i += 256) {
        int b = i >> 7, e = i & 127;
        tile[e * 65 + b] = emb[sid[b] * EE + e];
    }
    __syncthreads();
    float* dst = g_xT + s * (EE * BB);
    for (int i = t; i < 8192; i += 256)
        dst[i] = tile[(i >> 6) * 65 + (i & 63)];
}

__global__ void k_span(const int* offmap, const int* positions) {
    int idx = blockIdx.x * blockDim.x + threadIdx.x;
    if (idx >= BB * SS) return;
    int b = idx / SS;
    int s = idx % SS;
    int os = offmap[idx * 2], oe = offmap[idx * 2 + 1];
    unsigned m = 0;
    for (int p = 0; p < PP; p++) {
        int ps = positions[(b * PP + p) * 2];
        int pe = positions[(b * PP + p) * 2 + 1];
        if (os >= ps && oe <= pe) {
            m |= (1u << p);
            atomicAdd(&g_cnt[b * PP + p], 1);
        }
    }
    g_spanmaskT[s * BB + b] = m;
}

__device__ __forceinline__ void ffma2(unsigned long long& d,
                                      unsigned long long a,
                                      unsigned long long b) {
    asm("fma.rn.f32x2 %0, %1, %2, %0;" : "+l"(d) : "l"(a), "l"(b));
}
__device__ __forceinline__ void cpasync16(uint32_t saddr, const void* gaddr) {
    asm volatile("cp.async.cg.shared.global [%0], [%1], 16;" :: "r"(saddr), "l"(gaddr));
}
__device__ __forceinline__ void cpasync_commit() { asm volatile("cp.async.commit_group;"); }
__device__ __forceinline__ void cpasync_wait0()  { asm volatile("cp.async.wait_group 0;"); }
__device__ __forceinline__ void st_release_gpu(unsigned* p, unsigned v) {
    asm volatile("st.release.gpu.global.u32 [%0], %1;" :: "l"(p), "r"(v) : "memory");
}
__device__ __forceinline__ unsigned ld_acquire_gpu(const unsigned* p) {
    unsigned v;
    asm volatile("ld.acquire.gpu.global.u32 %0, [%1];" : "=r"(v) : "l"(p) : "memory");
    return v;
}
__device__ __forceinline__ void barx(int id, int cnt) {
    asm volatile("bar.sync %0, %1;" :: "r"(id), "r"(cnt) : "memory");
}
__device__ __forceinline__ void mb_init(uint32_t a, unsigned c) {
    asm volatile("mbarrier.init.shared.b64 [%0], %1;" :: "r"(a), "r"(c) : "memory");
}
__device__ __forceinline__ void mb_expect_tx(uint32_t a, unsigned bytes) {
    asm volatile("mbarrier.arrive.expect_tx.shared.b64 _, [%0], %1;"
                 :: "r"(a), "r"(bytes) : "memory");
}
__device__ __forceinline__ void mb_wait(uint32_t a, unsigned parity) {
    unsigned done;
    asm volatile(
        "{\n\t.reg .pred p;\n\t"
        "mbarrier.try_wait.parity.acquire.cta.shared::cta.b64 p, [%1], %2;\n\t"
        "selp.b32 %0, 1, 0, p;\n\t}"
        : "=r"(done) : "r"(a), "r"(parity) : "memory");
    if (!done) {
        asm volatile(
            "{\n\t.reg .pred P1;\n\t"
            "W_%=:\n\t"
            "mbarrier.try_wait.parity.acquire.cta.shared::cta.b64 P1, [%0], %1, 0x989680;\n\t"
            "@P1 bra.uni D_%=;\n\t"
            "bra.uni W_%=;\n\t"
            "D_%=:\n\t}"
            :: "r"(a), "r"(parity) : "memory");
    }
}
__device__ __forceinline__ void bulkcp(uint32_t dst, const void* src,
                                       unsigned bytes, uint32_t mbar) {
    asm volatile(
        "cp.async.bulk.shared::cta.global.mbarrier::complete_tx::bytes [%0], [%1], %2, [%3];"
        :: "r"(dst), "l"(src), "r"(bytes), "r"(mbar) : "memory");
}
__device__ __forceinline__ float sigmoidf_(float x) { return 1.f / (1.f + __expf(-x)); }
__device__ __forceinline__ float tanhf_(float x) {
    float xc = fminf(fmaxf(x, -15.f), 15.f);
    float e = __expf(2.f * xc);
    return (e - 1.f) / (e + 1.f);
}

__device__ __forceinline__ void gemm_range(const float* __restrict__ sAct,
                                           const float* __restrict__ sW2,
                                           int ct, int b0, int kbeg, int kend,
                                           unsigned long long acc[4][2]) {
    const float* abase = sAct + b0;
    #pragma unroll 2
    for (int k = kbeg; k < kend; k += 4) {
        ulonglong2 a0 = *(const ulonglong2*)(abase + (k + 0) * BB);
        ulonglong2 a1 = *(const ulonglong2*)(abase + (k + 1) * BB);
        ulonglong2 a2 = *(const ulonglong2*)(abase + (k + 2) * BB);
        ulonglong2 a3 = *(const ulonglong2*)(abase + (k + 3) * BB);
        #pragma unroll
        for (int r = 0; r < 4; r++) {
            const float* wb = sW2 + (ct * 4 + r) * SWS2 + k * 2;
            ulonglong2 w01 = *(const ulonglong2*)(wb);
            ulonglong2 w23 = *(const ulonglong2*)(wb + 4);
            ffma2(acc[r][0], w01.x, a0.x); ffma2(acc[r][1], w01.x, a0.y);
            ffma2(acc[r][0], w01.y, a1.x); ffma2(acc[r][1], w01.y, a1.y);
            ffma2(acc[r][0], w23.x, a2.x); ffma2(acc[r][1], w23.x, a2.y);
            ffma2(acc[r][0], w23.y, a3.x); ffma2(acc[r][1], w23.y, a3.y);
        }
    }
}

extern __shared__ float smem[];

__global__ void __launch_bounds__(512, 1) k_lstm(int nsteps) {
    float*    sAct = smem + SM_ACT;              // [384][64]
    float*    sW2  = smem + SM_W;                // [16][SWS2]
    float*    sZP  = smem + SM_Z;                // [8 kq][16][64]
    float*    sR   = smem + SM_R;                // [32 p][4 u][64 b]
    unsigned* sM   = (unsigned*)(smem + SM_M);   // [2][64]

    const int t   = threadIdx.x;
    const int jb  = blockIdx.x & (NJB - 1);
    const int dir = blockIdx.x >> 6;
    unsigned* slots = g_arrive + dir * NJB;

    const uint32_t sact_b = (uint32_t)__cvta_generic_to_shared(sAct);
    const uint32_t sm_b   = (uint32_t)__cvta_generic_to_shared(sM);
    const uint32_t mbA    = (uint32_t)__cvta_generic_to_shared(smem + SM_MB);
    const uint32_t mbB    = mbA + 8;

    if (t == 0) { mb_init(mbA, 1); mb_init(mbB, 1); }

    {   // weights resident in smem for the whole run
        const float4* wsrc = (const float4*)(g_Wt + (size_t)(dir * NJB + jb) * 16 * 384 * 2);
        float4* wdst = (float4*)sW2;
        for (int i = t; i < 3072; i += 512) {
            int c = i / 192, j = i % 192;
            wdst[c * (SWS2 / 4) + j] = wsrc[i];
        }
    }
    for (int i = t; i < 8192; i += 512) sR[i] = 0.f;

    // roles
    const int kq    = t >> 6;          // warp-pair id 0..7
    const int tp    = t & 63;
    const int ct    = tp >> 4;         // gate 0..3
    const int b0    = (tp & 15) * 4;
    const int hb    = 128 + kq * 32;   // h K-range (32 rows per pair)
    const int xb    = kq * 16;         // x K-range (16 rows per pair)
    const int pbar  = 8 + kq;          // named barrier per pair
    const uint32_t myMB = (kq < 4) ? mbA : mbB;   // wave A = pairs 0-3 (h rows 128..255)

    // gates roles (t<256): 1 cell per thread
    const int u  = (t >> 6) & 3;
    const int gb = t & 63;
    float bvg[4];
    if (t < 256) {
        #pragma unroll
        for (int g = 0; g < 4; g++)
            bvg[g] = g_bias[dir * G4 + g * HH + jb * 4 + u];
    }
    float creg = 0.f;

    unsigned long long acc[4][2];

    // prologue: x(0) + mask(0); x-GEMM(0); then prefetch x(1)
    {
        int s0 = dir ? (SS - 1) : 0;
        const float* xsrc = g_xT + (size_t)s0 * (EE * BB);
        #pragma unroll
        for (int i = 0; i < 4; i++) {
            int fi = kq * 1024 + (i * 64 + tp) * 4;
            cpasync16(sact_b + (uint32_t)fi * 4, xsrc + fi);
        }
        if (t < 16)
            cpasync16(sm_b + (uint32_t)t * 16, g_spanmaskT + s0 * BB + t * 4);
        cpasync_commit();
    }
    cpasync_wait0();
    __syncthreads();   // also orders mbarrier init before any bulk issue
    #pragma unroll
    for (int r = 0; r < 4; r++) { acc[r][0] = 0ull; acc[r][1] = 0ull; }
    gemm_range(sAct, sW2, ct, b0, xb, xb + 16, acc);
    barx(pbar, 64);                    // pair done reading x(0) slice
    if (nsteps > 1) {                  // prefetch x(1)
        int s1 = dir ? (SS - 2) : 1;
        const float* xsrc = g_xT + (size_t)s1 * (EE * BB);
        #pragma unroll
        for (int i = 0; i < 4; i++) {
            int fi = kq * 1024 + (i * 64 + tp) * 4;
            cpasync16(sact_b + (uint32_t)fi * 4, xsrc + fi);
        }
    }
    cpasync_commit();

    for (int step = 0; step < nsteps; step++) {
        const int par = step & 1;

        // 1. slot barrier (only 64 threads poll)
        if (t < NJB) {
            while ((int)ld_acquire_gpu(slots + t) < step) { }
        }
        __syncthreads();

        // 2. bulk-async h staging: two 32KB waves on two mbarriers
        if (t == 0) {
            const float* hsrc = g_h + (dir * 2 + par) * (HH * BB);
            mb_expect_tx(mbA, 32768);
            bulkcp(sact_b + 8192 * 4, hsrc, 32768, mbA);           // h rows 128..255
            mb_expect_tx(mbB, 32768);
            bulkcp(sact_b + 16384 * 4, hsrc + 8192, 32768, mbB);   // h rows 256..383
        }

        // 3. x + mask prefetch for step+1 (sole cp.async group)
        if (step + 1 < nsteps) {
            int s_next = dir ? (SS - 2 - step) : (step + 1);
            const float* xsrc = g_xT + (size_t)s_next * (EE * BB);
            #pragma unroll
            for (int i = 0; i < 4; i++) {
                int fi = kq * 1024 + (i * 64 + tp) * 4;
                cpasync16(sact_b + (uint32_t)fi * 4, xsrc + fi);
            }
            if (t < 16)
                cpasync16(sm_b + (uint32_t)((par ^ 1) * 64 + t * 4) * 4,
                          g_spanmaskT + s_next * BB + t * 4);
        }
        cpasync_commit();

        // 4. wait own wave's mbarrier; full 32-row h-GEMM
        mb_wait(myMB, (unsigned)par);
        gemm_range(sAct, sW2, ct, b0, hb, hb + 32, acc);

        // 5. K-eighth partials; block-wide join
        #pragma unroll
        for (int r = 0; r < 4; r++) {
            float2 lo = *(float2*)&acc[r][0];
            float2 hi = *(float2*)&acc[r][1];
            *(float4*)&sZP[kq * 1024 + (ct * 4 + r) * 64 + b0] =
                make_float4(lo.x, lo.y, hi.x, hi.y);
        }
        #pragma unroll
        for (int r = 0; r < 4; r++) { acc[r][0] = 0ull; acc[r][1] = 0ull; }
        __syncthreads();

        // 6. gates (warps 0-7) -> h publish -> release; warps 8-15 skip ahead
        if (t < 256) {
            float z[4];
            #pragma unroll
            for (int g = 0; g < 4; g++) {
                float s = bvg[g];
                #pragma unroll
                for (int q = 0; q < 8; q++)
                    s += sZP[q * 1024 + (g * 4 + u) * 64 + gb];
                z[g] = s;
            }
            float ii = sigmoidf_(z[0]);
            float ff = sigmoidf_(z[1]);
            float gg = tanhf_(z[2]);
            float oo = sigmoidf_(z[3]);
            float cn = ff * creg + ii * gg;
            creg = cn;
            float hn = oo * tanhf_(cn);
            int j = jb * 4 + u;
            __stcg(&g_h[((dir * 2 + (par ^ 1)) * HH + j) * BB + gb], hn);
            barx(1, 256);
            if (t == 0) {
                asm volatile("membar.gl;" ::: "memory");
                st_release_gpu(slots + jb, (unsigned)(step + 1));
            }
            // off-critical-path span accumulation
            unsigned m = sM[par * 64 + gb];
            while (m) {
                int p = __ffs(m) - 1;
                m &= m - 1;
                sR[p * 256 + u * 64 + gb] += hn;
            }
        }

        // 7. trailing x-GEMM for step+1 (X group long since landed)
        cpasync_wait0();
        barx(pbar, 64);
        if (step + 1 < nsteps)
            gemm_range(sAct, sW2, ct, b0, xb, xb + 16, acc);
    }

    __syncthreads();
    for (int i = t; i < 8192; i += 512) {
        int p = i >> 8, uu = (i >> 6) & 3, b = i & 63;
        g_reps[(b * PP + p) * (2 * HH) + dir * HH + jb * 4 + uu] = sR[i];
    }
}

__global__ void k_final(const float* fc_w, const float* fc_b,
                        const int* positions, float* out) {
    int bp = blockIdx.x;
    int t = threadIdx.x;
    __shared__ float red[128];
    float s = 0.f;
    for (int d = t; d < 2 * HH; d += 128)
        s += g_reps[bp * (2 * HH) + d] * fc_w[d];
    red[t] = s;
    __syncthreads();
    for (int o = 64; o > 0; o >>= 1) {
        if (t < o) red[t] += red[t + o];
        __syncthreads();
    }
    if (t == 0) {
        int cnt = g_cnt[bp];
        int ps = positions[bp * 2], pe = positions[bp * 2 + 1];
        bool valid = (cnt > 0) && !(ps == 0 && pe == 0);
        float v = valid ? red[0] / fmaxf((float)cnt, 1.f) : 0.f;
        out[bp] = v + fc_b[0];
    }
}

extern "C" void kernel_launch(void* const* d_in, const int* in_sizes, int n_in,
                              void* d_out, int out_size) {
    const float* emb    = (const float*)d_in[0];
    const float* Wih_f  = (const float*)d_in[1];
    const float* Whh_f  = (const float*)d_in[2];
    const float* bih_f  = (const float*)d_in[3];
    const float* bhh_f  = (const float*)d_in[4];
    const float* Wih_b  = (const float*)d_in[5];
    const float* Whh_b  = (const float*)d_in[6];
    const float* bih_b  = (const float*)d_in[7];
    const float* bhh_b  = (const float*)d_in[8];
    const float* fc_w   = (const float*)d_in[9];
    const float* fc_b   = (const float*)d_in[10];
    const int* input_ids = (const int*)d_in[11];
    const int* offmap    = (const int*)d_in[13];
    const int* positions = (const int*)d_in[14];
    float* out = (float*)d_out;

    cudaFuncSetAttribute(k_lstm, cudaFuncAttributeMaxDynamicSharedMemorySize, SMEM_BYTES);

    k_prep<<<1024, 256>>>(bih_f, bhh_f, bih_b, bhh_b, Wih_f, Whh_f, Wih_b, Whh_b);
    k_embed<<<SS, 256>>>(emb, input_ids);
    k_span<<<(BB * SS) / 256, 256>>>(offmap, positions);
    k_lstm<<<NBLK, 512, SMEM_BYTES>>>(SS);
    k_final<<<BB * PP, 128>>>(fc_w, fc_b, positions, out);
}